// round 2
// baseline (speedup 1.0000x reference)
#include <cuda_runtime.h>

// Problem constants (fixed shapes for this problem instance)
#define NB 8
#define NP 64
#define NV 32
#define ND 1626
#define NT 256

#define LBF 1e-20f
#define UBF 1e+20f

__device__ __forceinline__ float fast_lg2(float x) {
    float r;
    asm("lg2.approx.ftz.f32 %0, %1;" : "=f"(r) : "f"(x));
    return r;
}
__device__ __forceinline__ float fast_ex2(float x) {
    float r;
    asm("ex2.approx.ftz.f32 %0, %1;" : "=f"(r) : "f"(x));
    return r;
}

// Directions computed once per launch in fp64 to match numpy exactly after fp32 cast.
__device__ float g_dirs[ND * 3];

__global__ void init_dirs_kernel() {
    int d = blockIdx.x * blockDim.x + threadIdx.x;
    if (d >= ND) return;
    const double PI = 3.141592653589793;  // fp64 nearest to pi (matches numpy)
    double step1 = PI / 29.0;             // linspace(-pi/2, pi/2, 30) step
    double step2 = (2.0 * PI) / 58.0;     // linspace(-pi, pi, 59) step
    double th1, th2;
    if (d < 1624) {
        int i1 = d / 58 + 1;        // th1 index 1..28 (interior rows)
        int i2 = d - (d / 58) * 58; // th2 index 0..57
        th1 = (double)i1 * step1 + (-PI * 0.5);
        th2 = (double)i2 * step2 + (-PI);
    } else {
        th1 = (d == 1624) ? (-PI * 0.5) : (PI * 0.5); // poles (linspace endpoints exact)
        th2 = -PI;
    }
    double c1 = cos(th1), s1 = sin(th1);
    double c2 = cos(th2), s2 = sin(th2);
    g_dirs[d * 3 + 0] = (float)(c1 * c2);
    g_dirs[d * 3 + 1] = (float)(c1 * s2);
    g_dirs[d * 3 + 2] = (float)s1;
}

__global__ __launch_bounds__(NT) void spt_kernel(
    const float* __restrict__ vertices,    // (B,P,V,3)
    const float* __restrict__ smoothness,  // (B,P)
    float* __restrict__ out)
{
    __shared__ float s_dirs[ND * 3];
    __shared__ float s_lv[NV * 3];
    __shared__ float s_mean[3];

    const int bp = blockIdx.x;   // 0..511 : (b*P + p)
    const int tid = threadIdx.x;

    // Stage directions into shared memory
    for (int i = tid; i < ND * 3; i += NT) s_dirs[i] = g_dirs[i];

    // Load vertices, compute mean, form local_v in place
    const float* vin = vertices + (size_t)bp * (NV * 3);
    if (tid < NV * 3) s_lv[tid] = vin[tid];
    __syncthreads();
    if (tid < 3) {
        float s = 0.0f;
        #pragma unroll
        for (int v = 0; v < NV; v++) s += s_lv[v * 3 + tid];
        s_mean[tid] = s * (1.0f / (float)NV);
    }
    __syncthreads();
    if (tid < NV * 3) s_lv[tid] -= s_mean[tid % 3];
    __syncthreads();

    // Output section pointers (tuple flattened in order)
    float* const out_points = out;                                    // B*P*D*3
    float* const out_dh     = out + (size_t)NB * NP * ND * 3;         // B*P*D*4
    float* const out_ov     = out + (size_t)NB * NP * ND * 7;         // B*P
    float* const out_re     = out_ov + NB * NP;                       // B*P
    float* const out_mean   = out_re + NB * NP;                       // B*P*3
    float* const out_lv     = out_mean + NB * NP * 3;                 // B*P*V*3

    if (tid == 0) { out_ov[bp] = 0.0f; out_re[bp] = 0.0f; }
    if (tid < 3)  out_mean[bp * 3 + tid] = s_mean[tid];
    if (tid < NV * 3) out_lv[(size_t)bp * (NV * 3) + tid] = s_lv[tid];

    const float p     = smoothness[bp];
    const float pm1   = p - 1.0f;
    const float inv_p = 1.0f / p;
    const float mx = s_mean[0], my = s_mean[1], mz = s_mean[2];

    for (int d = tid; d < ND; d += NT) {
        const float dx = s_dirs[d * 3 + 0];
        const float dy = s_dirs[d * 3 + 1];
        const float dz = s_dirs[d * 3 + 2];

        // Pass A: z = local_v . dir, zm = max(z,0), track max
        float zm[NV];
        float zmax = 0.0f;
        #pragma unroll
        for (int v = 0; v < NV; v++) {
            float z = s_lv[v * 3 + 0] * dx + s_lv[v * 3 + 1] * dy + s_lv[v * 3 + 2] * dz;
            z = fmaxf(z, 0.0f);
            zm[v] = z;
            zmax = fmaxf(zmax, z);
        }

        // Dynamic range rescale factor k (rarely != 1)
        float k = 1.0f;
        {
            const float LOG10_2 = 0.30102999566398119521f;
            float expo = fast_lg2(zmax) * LOG10_2 * p;   // log10(zmax)*p; -inf if zmax==0
            if (expo < -20.0f) {
                float n = ceilf((-15.0f - expo) / p);    // +inf -> ceil inf
                n = fminf(fmaxf(n, 0.0f), 20.0f);
                // k = 10^n, n integer in [0,20]
                const float LOG2_10 = 3.32192809488736234787f;
                k = fast_ex2(n * LOG2_10);
            }
        }

        // Pass B: zm_p = clip((zm*k)^p), sum; cache e = (zm*k)^(p-1) in zm[]
        float sum = 0.0f;
        #pragma unroll
        for (int v = 0; v < NV; v++) {
            float zk = zm[v] * k;
            float l  = fast_lg2(zk);          // -inf for zk==0
            float e  = fast_ex2(pm1 * l);     // zk^(p-1); 0 for zk==0
            zm[v] = e;
            float zp = fminf(fmaxf(e * zk, LBF), UBF);   // clip(zk^p)
            sum += (zk > 0.0f) ? zp : 0.0f;
        }

        // h = clip(sum^(1/p)); h1mp = h^(1-p)
        float h, h1mp;
        if (sum > 0.0f) {
            h = fast_ex2(inv_p * fast_lg2(sum));
            h = fminf(fmaxf(h, LBF), UBF);
            h1mp = fast_ex2(-pm1 * fast_lg2(h));   // bounded: sum>=1e-20 -> h^(1-p)<=1e20
        } else {
            h = LBF;
            h1mp = 0.0f;
        }

        // Pass C: dhdz = clip(e * h^(1-p), LB, UB)  [= clip(ratio^(p-1))],
        //         zk==0 lanes give e=0 -> clipped up to LB, matching reference's LB fill.
        float ax = 0.0f, ay = 0.0f, az = 0.0f;
        #pragma unroll
        for (int v = 0; v < NV; v++) {
            float dh = fminf(fmaxf(zm[v] * h1mp, LBF), UBF);
            ax += dh * s_lv[v * 3 + 0];
            ay += dh * s_lv[v * 3 + 1];
            az += dh * s_lv[v * 3 + 2];
        }

        const size_t base = (size_t)bp * ND + d;
        out_points[base * 3 + 0] = ax + mx;
        out_points[base * 3 + 1] = ay + my;
        out_points[base * 3 + 2] = az + mz;

        float hout = h / k;
        hout = fminf(fmaxf(hout, -UBF), UBF);
        reinterpret_cast<float4*>(out_dh)[base] = make_float4(dx, dy, dz, hout);
    }
}

extern "C" void kernel_launch(void* const* d_in, const int* in_sizes, int n_in,
                              void* d_out, int out_size) {
    const float* vertices   = (const float*)d_in[0];   // (8,64,32,3)
    const float* smoothness = (const float*)d_in[1];   // (8,64)
    // d_in[2] = pointcloud, unused by the reference outputs
    float* out = (float*)d_out;

    init_dirs_kernel<<<(ND + 255) / 256, 256>>>();
    spt_kernel<<<NB * NP, NT>>>(vertices, smoothness, out);
}

// round 3
// speedup vs baseline: 1.6181x; 1.6181x over previous
#include <cuda_runtime.h>

// Fixed problem shapes
#define NB 8
#define NP 64
#define NV 32
#define ND 1626
#define NT 128
#define NHALF 813          // directions per half-block
#define NITER 7            // ceil(813/128)

__device__ float4 g_dirs4[ND];   // (dx,dy,dz,0) per direction, fp64-accurate

__device__ __forceinline__ float fast_lg2(float x) {
    float r; asm("lg2.approx.ftz.f32 %0, %1;" : "=f"(r) : "f"(x)); return r;
}
__device__ __forceinline__ float fast_ex2(float x) {
    float r; asm("ex2.approx.ftz.f32 %0, %1;" : "=f"(r) : "f"(x)); return r;
}

// One small block: 89 fp64 sincos into smem, then 1626 fp64 products.
// Matches numpy linspace (fp64, exact endpoints) + fp64 outer, cast to fp32.
__global__ void init_dirs_kernel() {
    __shared__ double c1[30], s1[30], c2[59], s2[59];
    const double PI = 3.141592653589793;
    int tid = threadIdx.x;
    if (tid < 30) {
        double th = (tid == 0)  ? -PI * 0.5
                  : (tid == 29) ?  PI * 0.5
                  : (double)tid * (PI / 29.0) + (-PI * 0.5);
        c1[tid] = cos(th); s1[tid] = sin(th);
    } else if (tid < 89) {
        int i = tid - 30;
        double th = (i == 0) ? -PI : (double)i * (2.0 * PI / 58.0) + (-PI);
        c2[i] = cos(th); s2[i] = sin(th);
    }
    __syncthreads();
    for (int d = tid; d < ND; d += blockDim.x) {
        double dx, dy, dz;
        if (d < 1624) {
            int i1 = d / 58 + 1, i2 = d % 58;
            dx = c1[i1] * c2[i2]; dy = c1[i1] * s2[i2]; dz = s1[i1];
        } else if (d == 1624) {
            dx = c1[0] * c2[0];   dy = c1[0] * s2[0];   dz = s1[0];
        } else {
            dx = c1[29] * c2[0];  dy = c1[29] * s2[0];  dz = s1[29];
        }
        g_dirs4[d] = make_float4((float)dx, (float)dy, (float)dz, 0.0f);
    }
}

__global__ __launch_bounds__(NT, 7) void spt_kernel(
    const float* __restrict__ vertices,    // (B,P,V,3)
    const float* __restrict__ smoothness,  // (B,P)
    float* __restrict__ out)
{
    __shared__ __align__(16) float s_x[NV], s_y[NV], s_z[NV];
    __shared__ float s_aos[NV * 3];
    __shared__ float s_mean[3];

    const int blk  = blockIdx.x;
    const int bp   = blk >> 1;        // tile index 0..511
    const int half = blk & 1;         // which 813-direction half
    const int tid  = threadIdx.x;

    // Load vertices (AoS), mean, build mean-centered SoA
    const float* vin = vertices + (size_t)bp * (NV * 3);
    if (tid < NV * 3) s_aos[tid] = vin[tid];
    __syncthreads();
    if (tid < 3) {
        float s = 0.0f;
        #pragma unroll
        for (int v = 0; v < NV; v++) s += s_aos[v * 3 + tid];
        s_mean[tid] = s * (1.0f / (float)NV);
    }
    __syncthreads();

    // Output sections (tuple flattened in reference order)
    float* const out_points = out;                                  // B*P*D*3
    float* const out_dh     = out + (size_t)NB * NP * ND * 3;       // B*P*D*4
    float* const out_ov     = out + (size_t)NB * NP * ND * 7;       // B*P
    float* const out_re     = out_ov + NB * NP;                     // B*P
    float* const out_mean   = out_re + NB * NP;                     // B*P*3
    float* const out_lv     = out_mean + NB * NP * 3;               // B*P*V*3

    if (tid < NV * 3) {
        int c = tid / NV, v = tid - c * NV;                 // c in 0..2, v in 0..31
        float val = s_aos[v * 3 + c] - s_mean[c];
        (c == 0 ? s_x : (c == 1 ? s_y : s_z))[v] = val;
        if (half == 0) out_lv[(size_t)bp * (NV * 3) + v * 3 + c] = val;
    }
    if (half == 0) {
        if (tid == 0) { out_ov[bp] = 0.0f; out_re[bp] = 0.0f; }
        if (tid < 3)  out_mean[bp * 3 + tid] = s_mean[tid];
    }
    __syncthreads();

    const float p    = smoothness[bp];
    const float pm1  = p - 1.0f;
    const float invp = 1.0f / p;
    const float rco  = invp - 1.0f;     // -(p-1)/p
    const float mx = s_mean[0], my = s_mean[1], mz = s_mean[2];

    const float4* x4 = reinterpret_cast<const float4*>(s_x);
    const float4* y4 = reinterpret_cast<const float4*>(s_y);
    const float4* z4 = reinterpret_cast<const float4*>(s_z);

    #pragma unroll 1
    for (int it = 0; it < NITER; it++) {
        int i = it * NT + tid;
        if (i >= NHALF) break;
        int d = half * NHALF + i;

        float4 dv = g_dirs4[d];
        const float dx = dv.x, dy = dv.y, dz = dv.z;

        // Pass A: zmax = max_v max(dot,0); floor avoids -inf log downstream
        float zmax = 1e-30f;
        #pragma unroll
        for (int j = 0; j < NV / 4; j++) {
            float4 X = x4[j], Y = y4[j], Z = z4[j];
            zmax = fmaxf(zmax, fmaf(dz, Z.x, fmaf(dy, Y.x, dx * X.x)));
            zmax = fmaxf(zmax, fmaf(dz, Z.y, fmaf(dy, Y.y, dx * X.y)));
            zmax = fmaxf(zmax, fmaf(dz, Z.z, fmaf(dy, Y.z, dx * X.z)));
            zmax = fmaxf(zmax, fmaf(dz, Z.w, fmaf(dy, Y.w, dx * X.w)));
        }
        const float lg2max = fast_lg2(zmax);
        const float c0 = -pm1 * lg2max;

        // Pass B: e = (z/zmax)^(p-1); sum' = Σ e*z; a = Σ e*lv
        float sum = 0.0f, ax = 0.0f, ay = 0.0f, az = 0.0f;
        #pragma unroll
        for (int j = 0; j < NV / 4; j++) {
            float4 X = x4[j], Y = y4[j], Z = z4[j];
            {
                float zc = fmaxf(fmaf(dz, Z.x, fmaf(dy, Y.x, dx * X.x)), 0.0f);
                float e  = fast_ex2(fmaf(pm1, fast_lg2(zc), c0));
                sum = fmaf(e, zc, sum);
                ax = fmaf(e, X.x, ax); ay = fmaf(e, Y.x, ay); az = fmaf(e, Z.x, az);
            }
            {
                float zc = fmaxf(fmaf(dz, Z.y, fmaf(dy, Y.y, dx * X.y)), 0.0f);
                float e  = fast_ex2(fmaf(pm1, fast_lg2(zc), c0));
                sum = fmaf(e, zc, sum);
                ax = fmaf(e, X.y, ax); ay = fmaf(e, Y.y, ay); az = fmaf(e, Z.y, az);
            }
            {
                float zc = fmaxf(fmaf(dz, Z.z, fmaf(dy, Y.z, dx * X.z)), 0.0f);
                float e  = fast_ex2(fmaf(pm1, fast_lg2(zc), c0));
                sum = fmaf(e, zc, sum);
                ax = fmaf(e, X.z, ax); ay = fmaf(e, Y.z, ay); az = fmaf(e, Z.z, az);
            }
            {
                float zc = fmaxf(fmaf(dz, Z.w, fmaf(dy, Y.w, dx * X.w)), 0.0f);
                float e  = fast_ex2(fmaf(pm1, fast_lg2(zc), c0));
                sum = fmaf(e, zc, sum);
                ax = fmaf(e, X.w, ax); ay = fmaf(e, Y.w, ay); az = fmaf(e, Z.w, az);
            }
        }

        // sum_u = sum'/zmax ; h_u = sum_u^(1/p) ; h1mp = h_u^(1-p) ; hout = zmax*h_u
        sum = fmaxf(sum, 1e-37f);                 // NaN guard (measure-zero case)
        float g    = fast_lg2(sum) - lg2max;      // log2(sum_u)
        float h_u  = fast_ex2(invp * g);
        float hout = zmax * h_u;
        float h1mp = fast_ex2(rco * g);

        const size_t base = (size_t)bp * ND + d;
        out_points[base * 3 + 0] = fmaf(ax, h1mp, mx);
        out_points[base * 3 + 1] = fmaf(ay, h1mp, my);
        out_points[base * 3 + 2] = fmaf(az, h1mp, mz);
        reinterpret_cast<float4*>(out_dh)[base] = make_float4(dx, dy, dz, hout);
    }
}

extern "C" void kernel_launch(void* const* d_in, const int* in_sizes, int n_in,
                              void* d_out, int out_size) {
    const float* vertices   = (const float*)d_in[0];   // (8,64,32,3)
    const float* smoothness = (const float*)d_in[1];   // (8,64)
    float* out = (float*)d_out;

    init_dirs_kernel<<<1, 256>>>();
    spt_kernel<<<NB * NP * 2, NT>>>(vertices, smoothness, out);
}

// round 4
// speedup vs baseline: 2.0682x; 1.2782x over previous
#include <cuda_runtime.h>

// Fixed problem shapes
#define NBATCH 8
#define NP 64
#define NV 32
#define ND 1626
#define NT 128
#define NHALF 813
#define NSA 407            // stream-A length per half
#define NSB 406            // stream-B length per half

__device__ float4 g_dirs4[ND];

__device__ __forceinline__ float fast_lg2(float x) {
    float r; asm("lg2.approx.ftz.f32 %0, %1;" : "=f"(r) : "f"(x)); return r;
}
__device__ __forceinline__ float fast_ex2(float x) {
    float r; asm("ex2.approx.ftz.f32 %0, %1;" : "=f"(r) : "f"(x)); return r;
}

// 16 blocks, each redundantly builds the small fp64 sincos tables (parallel across
// threads), then writes its ~102-direction slice. Matches numpy fp64 -> fp32 cast.
__global__ void init_dirs_kernel() {
    __shared__ double c1[30], s1[30], c2[59], s2[59];
    const double PI = 3.141592653589793;
    int tid = threadIdx.x;
    if (tid < 30) {
        double th = (tid == 0)  ? -PI * 0.5
                  : (tid == 29) ?  PI * 0.5
                  : (double)tid * (PI / 29.0) + (-PI * 0.5);
        c1[tid] = cos(th); s1[tid] = sin(th);
    } else if (tid < 89) {
        int i = tid - 30;
        double th = (i == 0) ? -PI : (double)i * (2.0 * PI / 58.0) + (-PI);
        c2[i] = cos(th); s2[i] = sin(th);
    }
    __syncthreads();
    if (tid < 102) {
        int d = blockIdx.x * 102 + tid;
        if (d < ND) {
            double dx, dy, dz;
            if (d < 1624) {
                int i1 = d / 58 + 1, i2 = d % 58;
                dx = c1[i1] * c2[i2]; dy = c1[i1] * s2[i2]; dz = s1[i1];
            } else if (d == 1624) {
                dx = c1[0] * c2[0];   dy = c1[0] * s2[0];   dz = s1[0];
            } else {
                dx = c1[29] * c2[0];  dy = c1[29] * s2[0];  dz = s1[29];
            }
            g_dirs4[d] = make_float4((float)dx, (float)dy, (float)dz, 0.0f);
        }
    }
}

__global__ __launch_bounds__(NT, 8) void spt_kernel(
    const float* __restrict__ vertices,    // (B,P,V,3)
    const float* __restrict__ smoothness,  // (B,P)
    float* __restrict__ out)
{
    __shared__ __align__(16) float s_x[NV], s_y[NV], s_z[NV];
    __shared__ float s_aos[NV * 3];
    __shared__ float s_mean[3];
    __shared__ float s_LR;

    const int blk  = blockIdx.x;
    const int bp   = blk >> 1;
    const int half = blk & 1;
    const int tid  = threadIdx.x;
    const int base = half * NHALF;

    // Load vertices (AoS), compute mean
    const float* vin = vertices + (size_t)bp * (NV * 3);
    if (tid < NV * 3) s_aos[tid] = vin[tid];
    __syncthreads();
    if (tid < 3) {
        float s = 0.0f;
        #pragma unroll
        for (int v = 0; v < NV; v++) s += s_aos[v * 3 + tid];
        s_mean[tid] = s * (1.0f / (float)NV);
    }
    __syncthreads();

    // Output sections (tuple flattened in reference order)
    float* const out_points = out;                                   // B*P*D*3
    float* const out_dh     = out + (size_t)NBATCH * NP * ND * 3;    // B*P*D*4
    float* const out_ov     = out + (size_t)NBATCH * NP * ND * 7;    // B*P
    float* const out_re     = out_ov + NBATCH * NP;                  // B*P
    float* const out_mean   = out_re + NBATCH * NP;                  // B*P*3
    float* const out_lv     = out_mean + NBATCH * NP * 3;            // B*P*V*3

    // Mean-centered SoA + small outputs
    if (tid < NV * 3) {
        int c = tid >> 5, v = tid & 31;
        float val = s_aos[v * 3 + c] - s_mean[c];
        (c == 0 ? s_x : (c == 1 ? s_y : s_z))[v] = val;
        if (half == 0) out_lv[(size_t)bp * (NV * 3) + v * 3 + c] = val;
    }
    if (half == 0) {
        if (tid == 0) { out_ov[bp] = 0.0f; out_re[bp] = 0.0f; }
        if (tid < 3)  out_mean[bp * 3 + tid] = s_mean[tid];
    }
    __syncthreads();

    // Per-tile radius: LR = lg2(max_v ||lv_v||) = 0.5*lg2(max ||lv||^2)
    if (tid < 32) {
        float r2 = s_x[tid] * s_x[tid] + s_y[tid] * s_y[tid] + s_z[tid] * s_z[tid];
        #pragma unroll
        for (int o = 16; o > 0; o >>= 1)
            r2 = fmaxf(r2, __shfl_xor_sync(0xFFFFFFFFu, r2, o));
        if (tid == 0) s_LR = 0.5f * fast_lg2(r2);
    }
    __syncthreads();

    const float p    = smoothness[bp];
    const float pm1  = p - 1.0f;
    const float invp = 1.0f / p;
    const float q    = pm1 * invp;
    const float LR   = s_LR;
    const float c0   = -pm1 * LR;     // e = ex2(pm1*lg2(z) + c0) = (z/R)^(p-1)
    const float qLR  = q * LR;
    const float mx = s_mean[0], my = s_mean[1], mz = s_mean[2];

    const float4* x4 = reinterpret_cast<const float4*>(s_x);
    const float4* y4 = reinterpret_cast<const float4*>(s_y);
    const float4* z4 = reinterpret_cast<const float4*>(s_z);

    #pragma unroll 1
    for (int it = 0; it < 4; it++) {
        const int idx = it * NT + tid;
        if (idx >= NSA) break;
        const bool hasB = (idx < NSB);
        const int dA = base + idx;
        const int dB = base + (hasB ? NSA + idx : idx);

        const float4 DA = g_dirs4[dA];
        const float4 DB = g_dirs4[dB];

        float S0 = 0.f, ax0 = 0.f, ay0 = 0.f, az0 = 0.f;
        float S1 = 0.f, ax1 = 0.f, ay1 = 0.f, az1 = 0.f;

        #pragma unroll
        for (int j = 0; j < NV / 4; j++) {
            float4 X = x4[j], Y = y4[j], Z = z4[j];
            #define STEP(C)                                                          \
            {                                                                        \
                float zA = fmaxf(fmaf(DA.z, Z.C, fmaf(DA.y, Y.C, DA.x * X.C)), 0.f); \
                float zB = fmaxf(fmaf(DB.z, Z.C, fmaf(DB.y, Y.C, DB.x * X.C)), 0.f); \
                float eA = fast_ex2(fmaf(pm1, fast_lg2(zA), c0));                    \
                float eB = fast_ex2(fmaf(pm1, fast_lg2(zB), c0));                    \
                S0  = fmaf(eA, zA,  S0);  S1  = fmaf(eB, zB,  S1);                   \
                ax0 = fmaf(eA, X.C, ax0); ax1 = fmaf(eB, X.C, ax1);                  \
                ay0 = fmaf(eA, Y.C, ay0); ay1 = fmaf(eB, Y.C, ay1);                  \
                az0 = fmaf(eA, Z.C, az0); az1 = fmaf(eB, Z.C, az1);                  \
            }
            STEP(x) STEP(y) STEP(z) STEP(w)
            #undef STEP
        }

        // Epilogue stream A:
        // hout = ex2(invp*LS + q*LR), scale = ex2(q*LR - q*LS)
        {
            float LS    = fast_lg2(fmaxf(S0, 1e-35f));
            float hout  = fast_ex2(fmaf(invp, LS, qLR));
            float scale = fast_ex2(fmaf(-q,   LS, qLR));
            const size_t b = (size_t)bp * ND + dA;
            out_points[b * 3 + 0] = fmaf(ax0, scale, mx);
            out_points[b * 3 + 1] = fmaf(ay0, scale, my);
            out_points[b * 3 + 2] = fmaf(az0, scale, mz);
            reinterpret_cast<float4*>(out_dh)[b] = make_float4(DA.x, DA.y, DA.z, hout);
        }
        if (hasB) {
            float LS    = fast_lg2(fmaxf(S1, 1e-35f));
            float hout  = fast_ex2(fmaf(invp, LS, qLR));
            float scale = fast_ex2(fmaf(-q,   LS, qLR));
            const size_t b = (size_t)bp * ND + dB;
            out_points[b * 3 + 0] = fmaf(ax1, scale, mx);
            out_points[b * 3 + 1] = fmaf(ay1, scale, my);
            out_points[b * 3 + 2] = fmaf(az1, scale, mz);
            reinterpret_cast<float4*>(out_dh)[b] = make_float4(DB.x, DB.y, DB.z, hout);
        }
    }
}

extern "C" void kernel_launch(void* const* d_in, const int* in_sizes, int n_in,
                              void* d_out, int out_size) {
    const float* vertices   = (const float*)d_in[0];   // (8,64,32,3)
    const float* smoothness = (const float*)d_in[1];   // (8,64)
    float* out = (float*)d_out;

    init_dirs_kernel<<<16, 128>>>();
    spt_kernel<<<NBATCH * NP * 2, NT>>>(vertices, smoothness, out);
}